// round 1
// baseline (speedup 1.0000x reference)
#include <cuda_runtime.h>
#include <cuda_bf16.h>
#include <cstdint>

#define USER_NUM 100000
#define ITEM_NUM 50000
#define NTOT     150000
#define EMB      64
#define N_EDGES  8000000
#define N_LAYERS 3
#define EPS_F    0.1f
#define PROTO    4000

// Ping-pong scratch for ego embeddings (38.4 MB each). __device__ globals:
// allocation-free per the harness rules.
__device__ float g_ego_a[(size_t)NTOT * EMB];
__device__ float g_ego_b[(size_t)NTOT * EMB];

// Vector reduction (no-return atomic add) — sm_90+ supports red.global.add.v4.f32.
__device__ __forceinline__ void red_add_v4(float* addr, float a, float b, float c, float d) {
    asm volatile("red.global.add.v4.f32 [%0], {%1, %2, %3, %4};"
                 :: "l"(addr), "f"(a), "f"(b), "f"(c), "f"(d)
                 : "memory");
}

// SPMM scatter: y[rows[e]] += vals[e] * x[cols[e]]   (y pre-zeroed)
// 16 threads per edge, float4 per thread (64 floats = 16 lanes x 4).
__global__ void __launch_bounds__(256) spmm_kernel(
    const int*   __restrict__ rows,
    const int*   __restrict__ cols,
    const float* __restrict__ vals,
    const float* __restrict__ x,
    float*       __restrict__ y)
{
    long long t = (long long)blockIdx.x * blockDim.x + threadIdx.x;
    long long e = t >> 4;
    if (e >= (long long)N_EDGES) return;
    int lane = (int)(t & 15);

    int   r = rows[e];
    int   c = cols[e];
    float v = vals[e];

    const float4 xv = *reinterpret_cast<const float4*>(x + (size_t)c * EMB + lane * 4);
    red_add_v4(y + (size_t)r * EMB + lane * 4,
               v * xv.x, v * xv.y, v * xv.z, v * xv.w);
}

__device__ __forceinline__ float signf3(float x) {
    return (x > 0.f) ? 1.f : ((x < 0.f) ? -1.f : 0.f);
}

// Fused: ego += sign(ego) * l2_normalize(noise_k) * EPS ; acc += ego / 3
// 16 threads per row; row-norm via shfl-xor over the 16-lane group.
__global__ void __launch_bounds__(256) noise_acc_kernel(
    const float* __restrict__ noise_k,
    float*       __restrict__ ego,
    float*       __restrict__ acc)
{
    long long t = (long long)blockIdx.x * blockDim.x + threadIdx.x;
    long long row = t >> 4;
    if (row >= (long long)NTOT) return;
    int lane = (int)(t & 15);
    size_t off = (size_t)row * EMB + lane * 4;

    float4 nv = *reinterpret_cast<const float4*>(noise_k + off);
    float ss = nv.x * nv.x + nv.y * nv.y + nv.z * nv.z + nv.w * nv.w;
    #pragma unroll
    for (int o = 8; o; o >>= 1)
        ss += __shfl_xor_sync(0xffffffffu, ss, o);

    float scale = EPS_F / fmaxf(sqrtf(ss), 1e-12f);

    float4 e = *reinterpret_cast<float4*>(ego + off);
    e.x += signf3(e.x) * nv.x * scale;
    e.y += signf3(e.y) * nv.y * scale;
    e.z += signf3(e.z) * nv.z * scale;
    e.w += signf3(e.w) * nv.w * scale;
    *reinterpret_cast<float4*>(ego + off) = e;

    const float inv3 = 1.0f / 3.0f;
    float4 a = *reinterpret_cast<float4*>(acc + off);
    a.x += e.x * inv3;
    a.y += e.y * inv3;
    a.z += e.z * inv3;
    a.w += e.w * inv3;
    *reinterpret_cast<float4*>(acc + off) = a;
}

extern "C" void kernel_launch(void* const* d_in, const int* in_sizes, int n_in,
                              void* d_out, int out_size)
{
    const float* user_emb   = (const float*)d_in[0];
    const float* item_emb   = (const float*)d_in[1];
    const float* user_proto = (const float*)d_in[2];
    const float* item_proto = (const float*)d_in[3];
    const int*   adj_rows   = (const int*)d_in[4];
    const int*   adj_cols   = (const int*)d_in[5];
    const float* adj_vals   = (const float*)d_in[6];
    const float* noise      = (const float*)d_in[7];
    float* out = (float*)d_out;

    float *ego_a, *ego_b;
    cudaGetSymbolAddress((void**)&ego_a, g_ego_a);
    cudaGetSymbolAddress((void**)&ego_b, g_ego_b);

    const size_t ego_bytes = (size_t)NTOT * EMB * sizeof(float);

    // ego_0 = concat(user_emb, item_emb)
    cudaMemcpyAsync(ego_a, user_emb, (size_t)USER_NUM * EMB * sizeof(float),
                    cudaMemcpyDeviceToDevice, 0);
    cudaMemcpyAsync(ego_a + (size_t)USER_NUM * EMB, item_emb,
                    (size_t)ITEM_NUM * EMB * sizeof(float),
                    cudaMemcpyDeviceToDevice, 0);

    // acc region of output starts at zero (d_out is poisoned by the harness)
    cudaMemsetAsync(out, 0, ego_bytes, 0);

    // Prototypes are passed through unchanged.
    cudaMemcpyAsync(out + (size_t)NTOT * EMB, user_proto,
                    (size_t)PROTO * EMB * sizeof(float), cudaMemcpyDeviceToDevice, 0);
    cudaMemcpyAsync(out + (size_t)(NTOT + PROTO) * EMB, item_proto,
                    (size_t)PROTO * EMB * sizeof(float), cudaMemcpyDeviceToDevice, 0);

    float* cur = ego_a;
    float* nxt = ego_b;

    const long long spmm_threads  = (long long)N_EDGES * 16;
    const int       spmm_blocks   = (int)((spmm_threads + 255) / 256);
    const long long noise_threads = (long long)NTOT * 16;
    const int       noise_blocks  = (int)((noise_threads + 255) / 256);

    for (int k = 0; k < N_LAYERS; k++) {
        cudaMemsetAsync(nxt, 0, ego_bytes, 0);
        spmm_kernel<<<spmm_blocks, 256>>>(adj_rows, adj_cols, adj_vals, cur, nxt);
        noise_acc_kernel<<<noise_blocks, 256>>>(
            noise + (size_t)k * NTOT * EMB, nxt, out);
        float* tmp = cur; cur = nxt; nxt = tmp;
    }
}

// round 2
// speedup vs baseline: 1.3877x; 1.3877x over previous
#include <cuda_runtime.h>
#include <cuda_bf16.h>
#include <cstdint>

#define USER_NUM 100000
#define ITEM_NUM 50000
#define NTOT     150000
#define EMB      64
#define N_EDGES  8000000
#define N_LAYERS 3
#define EPS_F    0.1f
#define PROTO    4000

// Ping-pong scratch for ego embeddings (38.4 MB each). __device__ globals:
// allocation-free per the harness rules.
__device__ float g_ego_a[(size_t)NTOT * EMB];
__device__ float g_ego_b[(size_t)NTOT * EMB];

// Vector reduction (no-return atomic add) — sm_90+ supports red.global.add.v4.f32.
__device__ __forceinline__ void red_add_v4(float* addr, float a, float b, float c, float d) {
    asm volatile("red.global.add.v4.f32 [%0], {%1, %2, %3, %4};"
                 :: "l"(addr), "f"(a), "f"(b), "f"(c), "f"(d)
                 : "memory");
}

// SPMM scatter: y[rows[e]] += vals[e] * x[cols[e]]   (y pre-zeroed)
// 16 threads per edge, float4 per thread (64 floats = 16 lanes x 4).
__global__ void __launch_bounds__(256) spmm_kernel(
    const int*   __restrict__ rows,
    const int*   __restrict__ cols,
    const float* __restrict__ vals,
    const float* __restrict__ x,
    float*       __restrict__ y)
{
    long long t = (long long)blockIdx.x * blockDim.x + threadIdx.x;
    long long e = t >> 4;
    if (e >= (long long)N_EDGES) return;
    int lane = (int)(t & 15);

    int   r = rows[e];
    int   c = cols[e];
    float v = vals[e];

    const float4 xv = *reinterpret_cast<const float4*>(x + (size_t)c * EMB + lane * 4);
    red_add_v4(y + (size_t)r * EMB + lane * 4,
               v * xv.x, v * xv.y, v * xv.z, v * xv.w);
}

__device__ __forceinline__ float signf3(float x) {
    return (x > 0.f) ? 1.f : ((x < 0.f) ? -1.f : 0.f);
}

// Fused: ego += sign(ego) * l2_normalize(noise_k) * EPS ; acc += ego / 3
// 16 threads per row; row-norm via shfl-xor over the 16-lane group.
__global__ void __launch_bounds__(256) noise_acc_kernel(
    const float* __restrict__ noise_k,
    float*       __restrict__ ego,
    float*       __restrict__ acc)
{
    long long t = (long long)blockIdx.x * blockDim.x + threadIdx.x;
    long long row = t >> 4;
    if (row >= (long long)NTOT) return;
    int lane = (int)(t & 15);
    size_t off = (size_t)row * EMB + lane * 4;

    float4 nv = *reinterpret_cast<const float4*>(noise_k + off);
    float ss = nv.x * nv.x + nv.y * nv.y + nv.z * nv.z + nv.w * nv.w;
    #pragma unroll
    for (int o = 8; o; o >>= 1)
        ss += __shfl_xor_sync(0xffffffffu, ss, o);

    float scale = EPS_F / fmaxf(sqrtf(ss), 1e-12f);

    float4 e = *reinterpret_cast<float4*>(ego + off);
    e.x += signf3(e.x) * nv.x * scale;
    e.y += signf3(e.y) * nv.y * scale;
    e.z += signf3(e.z) * nv.z * scale;
    e.w += signf3(e.w) * nv.w * scale;
    *reinterpret_cast<float4*>(ego + off) = e;

    const float inv3 = 1.0f / 3.0f;
    float4 a = *reinterpret_cast<float4*>(acc + off);
    a.x += e.x * inv3;
    a.y += e.y * inv3;
    a.z += e.z * inv3;
    a.w += e.w * inv3;
    *reinterpret_cast<float4*>(acc + off) = a;
}

extern "C" void kernel_launch(void* const* d_in, const int* in_sizes, int n_in,
                              void* d_out, int out_size)
{
    const float* user_emb   = (const float*)d_in[0];
    const float* item_emb   = (const float*)d_in[1];
    const float* user_proto = (const float*)d_in[2];
    const float* item_proto = (const float*)d_in[3];
    const int*   adj_rows   = (const int*)d_in[4];
    const int*   adj_cols   = (const int*)d_in[5];
    const float* adj_vals   = (const float*)d_in[6];
    const float* noise      = (const float*)d_in[7];
    float* out = (float*)d_out;

    float *ego_a, *ego_b;
    cudaGetSymbolAddress((void**)&ego_a, g_ego_a);
    cudaGetSymbolAddress((void**)&ego_b, g_ego_b);

    const size_t ego_bytes = (size_t)NTOT * EMB * sizeof(float);

    // ego_0 = concat(user_emb, item_emb)
    cudaMemcpyAsync(ego_a, user_emb, (size_t)USER_NUM * EMB * sizeof(float),
                    cudaMemcpyDeviceToDevice, 0);
    cudaMemcpyAsync(ego_a + (size_t)USER_NUM * EMB, item_emb,
                    (size_t)ITEM_NUM * EMB * sizeof(float),
                    cudaMemcpyDeviceToDevice, 0);

    // acc region of output starts at zero (d_out is poisoned by the harness)
    cudaMemsetAsync(out, 0, ego_bytes, 0);

    // Prototypes are passed through unchanged.
    cudaMemcpyAsync(out + (size_t)NTOT * EMB, user_proto,
                    (size_t)PROTO * EMB * sizeof(float), cudaMemcpyDeviceToDevice, 0);
    cudaMemcpyAsync(out + (size_t)(NTOT + PROTO) * EMB, item_proto,
                    (size_t)PROTO * EMB * sizeof(float), cudaMemcpyDeviceToDevice, 0);

    float* cur = ego_a;
    float* nxt = ego_b;

    const long long spmm_threads  = (long long)N_EDGES * 16;
    const int       spmm_blocks   = (int)((spmm_threads + 255) / 256);
    const long long noise_threads = (long long)NTOT * 16;
    const int       noise_blocks  = (int)((noise_threads + 255) / 256);

    for (int k = 0; k < N_LAYERS; k++) {
        cudaMemsetAsync(nxt, 0, ego_bytes, 0);
        spmm_kernel<<<spmm_blocks, 256>>>(adj_rows, adj_cols, adj_vals, cur, nxt);
        noise_acc_kernel<<<noise_blocks, 256>>>(
            noise + (size_t)k * NTOT * EMB, nxt, out);
        float* tmp = cur; cur = nxt; nxt = tmp;
    }
}

// round 3
// speedup vs baseline: 2.1830x; 1.5731x over previous
#include <cuda_runtime.h>
#include <cuda_bf16.h>
#include <cstdint>

#define USER_NUM 100000
#define ITEM_NUM 50000
#define NTOT     150000
#define EMB      64
#define N_EDGES  8000000
#define N_LAYERS 3
#define EPS_F    0.1f
#define PROTO    4000

// ---- device scratch (allocation-free) ----
__device__ float g_ego_a[(size_t)NTOT * EMB];       // 38.4 MB
__device__ float g_ego_b[(size_t)NTOT * EMB];       // 38.4 MB
__device__ int2  g_edges [(size_t)N_EDGES];         // 64 MB  {col, val_bits} sorted by row
__device__ int   g_count [NTOT];
__device__ int   g_rstart[NTOT + 1];
__device__ int   g_cursor[NTOT];

// ---------------- CSR build ----------------

__global__ void __launch_bounds__(256) hist_kernel(const int* __restrict__ rows)
{
    int e = blockIdx.x * blockDim.x + threadIdx.x;
    if (e >= N_EDGES) return;
    atomicAdd(&g_count[rows[e]], 1);
}

// Single-block exclusive scan of g_count -> g_rstart / g_cursor.
__global__ void __launch_bounds__(1024) scan_kernel()
{
    __shared__ int warp_sums[32];
    const int T  = 1024;
    const int CH = (NTOT + T - 1) / T;   // 147
    int tid  = threadIdx.x;
    int lane = tid & 31, wid = tid >> 5;

    int begin = tid * CH;
    int endi  = begin + CH; if (endi > NTOT) endi = NTOT;

    int s = 0;
    for (int i = begin; i < endi; i++) s += g_count[i];

    // inclusive warp scan of per-thread sums
    int v = s;
    #pragma unroll
    for (int o = 1; o < 32; o <<= 1) {
        int t = __shfl_up_sync(0xffffffffu, v, o);
        if (lane >= o) v += t;
    }
    if (lane == 31) warp_sums[wid] = v;
    __syncthreads();
    if (wid == 0) {
        int w = warp_sums[lane];
        #pragma unroll
        for (int o = 1; o < 32; o <<= 1) {
            int t = __shfl_up_sync(0xffffffffu, w, o);
            if (lane >= o) w += t;
        }
        warp_sums[lane] = w;
    }
    __syncthreads();

    int excl = (v - s) + (wid > 0 ? warp_sums[wid - 1] : 0);

    int run = excl;
    for (int i = begin; i < endi; i++) {
        g_rstart[i] = run;
        g_cursor[i] = run;
        run += g_count[i];
    }
    if (tid == T - 1) g_rstart[NTOT] = N_EDGES;
}

__global__ void __launch_bounds__(256) fill_kernel(
    const int*   __restrict__ rows,
    const int*   __restrict__ cols,
    const float* __restrict__ vals)
{
    int e = blockIdx.x * blockDim.x + threadIdx.x;
    if (e >= N_EDGES) return;
    int r   = rows[e];
    int pos = atomicAdd(&g_cursor[r], 1);
    g_edges[pos] = make_int2(cols[e], __float_as_int(vals[e]));
}

// ---------------- fused gather-SPMM + noise + accumulate ----------------
// One warp per row. Lane l owns columns {2l, 2l+1} (float2).
// new_row = sum_e val_e * x[col_e]            (gather, CSR)
// ego     = new_row + sign(new_row) * l2n(noise_row) * EPS
// acc    += ego / 3 ; optionally write ego for the next layer.

__device__ __forceinline__ float signf3(float x) {
    return (x > 0.f) ? 1.f : ((x < 0.f) ? -1.f : 0.f);
}

template<bool WRITE_EGO>
__global__ void __launch_bounds__(256) gather_layer_kernel(
    const float* __restrict__ x,        // ego in  [NTOT][64]
    const float* __restrict__ noise_k,  // [NTOT][64]
    float*       __restrict__ ego_out,  // ego out (next layer input)
    float*       __restrict__ acc)      // output accumulator
{
    int gwarp = (blockIdx.x * blockDim.x + threadIdx.x) >> 5;
    if (gwarp >= NTOT) return;
    int lane = threadIdx.x & 31;
    int row  = gwarp;

    int start = g_rstart[row];
    int end   = g_rstart[row + 1];

    const float2* __restrict__ x2 = reinterpret_cast<const float2*>(x);
    float accx = 0.f, accy = 0.f;

    for (int base = start; base < end; base += 32) {
        int n = end - base; if (n > 32) n = 32;
        int2 ed = make_int2(0, 0);
        if (lane < n) ed = g_edges[base + lane];

        for (int j = 0; j < n; j++) {
            int   col = __shfl_sync(0xffffffffu, ed.x, j);
            float v   = __int_as_float(__shfl_sync(0xffffffffu, ed.y, j));
            float2 xv = x2[(size_t)col * 32 + lane];
            accx += v * xv.x;
            accy += v * xv.y;
        }
    }

    size_t off = (size_t)row * EMB + lane * 2;

    float2 nv = *reinterpret_cast<const float2*>(noise_k + off);
    float ss = nv.x * nv.x + nv.y * nv.y;
    #pragma unroll
    for (int o = 16; o; o >>= 1)
        ss += __shfl_xor_sync(0xffffffffu, ss, o);
    float scale = EPS_F / fmaxf(sqrtf(ss), 1e-12f);

    float ex = accx + signf3(accx) * nv.x * scale;
    float ey = accy + signf3(accy) * nv.y * scale;

    if (WRITE_EGO) {
        *reinterpret_cast<float2*>(ego_out + off) = make_float2(ex, ey);
    }

    const float inv3 = 1.0f / 3.0f;
    float2 a = *reinterpret_cast<float2*>(acc + off);
    a.x += ex * inv3;
    a.y += ey * inv3;
    *reinterpret_cast<float2*>(acc + off) = a;
}

// ---------------- launch ----------------

extern "C" void kernel_launch(void* const* d_in, const int* in_sizes, int n_in,
                              void* d_out, int out_size)
{
    const float* user_emb   = (const float*)d_in[0];
    const float* item_emb   = (const float*)d_in[1];
    const float* user_proto = (const float*)d_in[2];
    const float* item_proto = (const float*)d_in[3];
    const int*   adj_rows   = (const int*)d_in[4];
    const int*   adj_cols   = (const int*)d_in[5];
    const float* adj_vals   = (const float*)d_in[6];
    const float* noise      = (const float*)d_in[7];
    float* out = (float*)d_out;

    float *ego_a, *ego_b; int *countp;
    cudaGetSymbolAddress((void**)&ego_a,  g_ego_a);
    cudaGetSymbolAddress((void**)&ego_b,  g_ego_b);
    cudaGetSymbolAddress((void**)&countp, g_count);

    const size_t ego_bytes = (size_t)NTOT * EMB * sizeof(float);

    // ego_0 = concat(user_emb, item_emb)
    cudaMemcpyAsync(ego_a, user_emb, (size_t)USER_NUM * EMB * sizeof(float),
                    cudaMemcpyDeviceToDevice, 0);
    cudaMemcpyAsync(ego_a + (size_t)USER_NUM * EMB, item_emb,
                    (size_t)ITEM_NUM * EMB * sizeof(float),
                    cudaMemcpyDeviceToDevice, 0);

    // acc region of output starts at zero
    cudaMemsetAsync(out, 0, ego_bytes, 0);

    // prototypes pass-through
    cudaMemcpyAsync(out + (size_t)NTOT * EMB, user_proto,
                    (size_t)PROTO * EMB * sizeof(float), cudaMemcpyDeviceToDevice, 0);
    cudaMemcpyAsync(out + (size_t)(NTOT + PROTO) * EMB, item_proto,
                    (size_t)PROTO * EMB * sizeof(float), cudaMemcpyDeviceToDevice, 0);

    // ---- CSR build (once per launch, reused for 3 layers) ----
    cudaMemsetAsync(countp, 0, NTOT * sizeof(int), 0);
    const int edge_blocks = (N_EDGES + 255) / 256;
    hist_kernel<<<edge_blocks, 256>>>(adj_rows);
    scan_kernel<<<1, 1024>>>();
    fill_kernel<<<edge_blocks, 256>>>(adj_rows, adj_cols, adj_vals);

    // ---- 3 fused gather layers ----
    const int row_warps  = NTOT;
    const int row_blocks = (row_warps * 32 + 255) / 256;

    gather_layer_kernel<true ><<<row_blocks, 256>>>(ego_a, noise,                          ego_b, out);
    gather_layer_kernel<true ><<<row_blocks, 256>>>(ego_b, noise + 1 * (size_t)NTOT * EMB, ego_a, out);
    gather_layer_kernel<false><<<row_blocks, 256>>>(ego_a, noise + 2 * (size_t)NTOT * EMB, ego_b, out);
}